// round 8
// baseline (speedup 1.0000x reference)
#include <cuda_runtime.h>
#include <cuda_fp16.h>
#include <math.h>
#include <cstdint>

#define BB 8
#define SS 2048
#define DD 1024
#define NEGC (-4294967295.0f)   // -(2^32) + 1

// ---------------------------------------------------------------------------
// Scratch (__device__ globals)
// ---------------------------------------------------------------------------
__device__ __half g_xh [(size_t)BB * SS * DD];    // x  (half)
__device__ __half g_wh [(size_t)3 * DD * DD];     // W^T (half, [N][K])
__device__ __half g_qh [(size_t)BB * SS * DD];    // q (half; also residual)
__device__ __half g_kh [(size_t)BB * SS * DD];
__device__ __half g_vh [(size_t)BB * SS * DD];
__device__ __half g_vth[(size_t)BB * SS * DD];    // v^T per batch: [B][D][S]
__device__ __half g_at [(size_t)BB * SS * SS];    // attn (half)
__device__ float  g_sc [(size_t)BB * SS * SS];    // scores (fp32)
__device__ float  g_mask[(size_t)BB * SS];

// ---------------------------------------------------------------------------
// PTX helpers
// ---------------------------------------------------------------------------
#define CPA16(sa, gp) asm volatile("cp.async.cg.shared.global [%0], [%1], 16;" :: "r"(sa), "l"(gp))
#define CPA_COMMIT()  asm volatile("cp.async.commit_group;" ::: "memory")
template <int N>
__device__ __forceinline__ void cpa_wait() { asm volatile("cp.async.wait_group %0;" :: "n"(N) : "memory"); }

__device__ __forceinline__ uint32_t smem_u32(const void* p) {
    uint32_t a;
    asm("{ .reg .u64 t; cvta.to.shared.u64 t, %1; cvt.u32.u64 %0, t; }" : "=r"(a) : "l"(p));
    return a;
}
__device__ __forceinline__ void mma_f16(float* c, const uint32_t* a, const uint32_t* b) {
    asm volatile(
        "mma.sync.aligned.m16n8k16.row.col.f32.f16.f16.f32 "
        "{%0,%1,%2,%3}, {%4,%5,%6,%7}, {%8,%9}, {%0,%1,%2,%3};"
        : "+f"(c[0]), "+f"(c[1]), "+f"(c[2]), "+f"(c[3])
        : "r"(a[0]), "r"(a[1]), "r"(a[2]), "r"(a[3]), "r"(b[0]), "r"(b[1]));
}
__device__ __forceinline__ void ldsm4(uint32_t& r0, uint32_t& r1, uint32_t& r2, uint32_t& r3,
                                      uint32_t addr) {
    asm volatile("ldmatrix.sync.aligned.m8n8.x4.shared.b16 {%0,%1,%2,%3}, [%4];"
                 : "=r"(r0), "=r"(r1), "=r"(r2), "=r"(r3) : "r"(addr));
}

// ---------------------------------------------------------------------------
// fp32 -> fp16 elementwise (x)
// ---------------------------------------------------------------------------
__global__ __launch_bounds__(256) void cvt_f2h(const float* __restrict__ src,
                                               __half* __restrict__ dst, int n4) {
    int i = blockIdx.x * 256 + threadIdx.x;
    int stride = gridDim.x * 256;
    __half2* d2 = (__half2*)dst;
    for (; i < n4; i += stride) {
        float4 v = reinterpret_cast<const float4*>(src)[i];
        d2[i * 2 + 0] = __floats2half2_rn(v.x, v.y);
        d2[i * 2 + 1] = __floats2half2_rn(v.z, v.w);
    }
}

// ---------------------------------------------------------------------------
// W [K][N] fp32  ->  W^T [N][K] half
// ---------------------------------------------------------------------------
__global__ __launch_bounds__(256) void transpose_w_h(const float* __restrict__ wq,
                                                     const float* __restrict__ wk,
                                                     const float* __restrict__ wv) {
    __shared__ float t[32][33];
    const float* src = (blockIdx.z == 0) ? wq : (blockIdx.z == 1) ? wk : wv;
    __half* dst = g_wh + (size_t)blockIdx.z * DD * DD;
    int f0 = blockIdx.x * 32, d0 = blockIdx.y * 32;
    #pragma unroll
    for (int i = threadIdx.y; i < 32; i += 8)
        t[i][threadIdx.x] = src[(size_t)(d0 + i) * DD + f0 + threadIdx.x];
    __syncthreads();
    #pragma unroll
    for (int i = threadIdx.y; i < 32; i += 8)
        dst[(size_t)(f0 + i) * DD + d0 + threadIdx.x] = __float2half_rn(t[threadIdx.x][i]);
}

// ---------------------------------------------------------------------------
// v [b][s][d] half -> vt [b][d][s] half
// ---------------------------------------------------------------------------
__global__ __launch_bounds__(256) void transpose_v_h() {
    __shared__ __half t[32][34];
    int b = blockIdx.z;
    int d0 = blockIdx.x * 32, s0 = blockIdx.y * 32;
    const __half* vb = g_vh + (size_t)b * SS * DD;
    __half* vtb = g_vth + (size_t)b * SS * DD;
    #pragma unroll
    for (int i = threadIdx.y; i < 32; i += 8)
        t[i][threadIdx.x] = vb[(size_t)(s0 + i) * DD + d0 + threadIdx.x];
    __syncthreads();
    #pragma unroll
    for (int i = threadIdx.y; i < 32; i += 8)
        vtb[(size_t)(d0 + i) * SS + s0 + threadIdx.x] = t[threadIdx.x][i];
}

// ---------------------------------------------------------------------------
// masks[b,s] = sin(|sum_d x|)  (from original fp32 x)
// ---------------------------------------------------------------------------
__global__ __launch_bounds__(256) void mask_kernel(const float* __restrict__ x) {
    int row = blockIdx.x;
    const float* xr = x + (size_t)row * DD;
    float s = 0.0f;
    for (int i = threadIdx.x; i < DD; i += 256) s += xr[i];
    #pragma unroll
    for (int o = 16; o > 0; o >>= 1) s += __shfl_xor_sync(0xffffffffu, s, o);
    __shared__ float ws[8];
    int w = threadIdx.x >> 5, l = threadIdx.x & 31;
    if (l == 0) ws[w] = s;
    __syncthreads();
    if (threadIdx.x == 0) {
        float t = 0.0f;
        #pragma unroll
        for (int i = 0; i < 8; i++) t += ws[i];
        g_mask[row] = (float)sin((double)fabsf(t));
    }
}

// ---------------------------------------------------------------------------
// fp16 tensor-core GEMM with ldmatrix fragment loads.
// C = A[M][K] * B[N][K]^T, both half, k-major.
// BM=BN=128, BK=64; 256 thr = 8 warps (2x4); warp tile 64x32; m16n8k16.
// ---------------------------------------------------------------------------
#define TS_H   72                               // halves per smem row (64 + 8 pad)
#define T_BYTES (128 * TS_H * 2)                // 18432
#define STAGE_BYTES (2 * T_BYTES)               // 36864
#define SMEM_TOTAL  (2 * STAGE_BYTES)           // 73728

__device__ __forceinline__ void load_h(uint32_t s, const __half* __restrict__ g,
                                       int ld, int tid) {
    #pragma unroll
    for (int i = 0; i < 4; i++) {
        int idx = tid + i * 256;
        int row = idx >> 3, c = idx & 7;
        CPA16(s + (uint32_t)(row * TS_H + c * 8) * 2, g + (size_t)row * ld + c * 8);
    }
}

template <int EPI>
__global__ __launch_bounds__(256, 2)
void hgemm(const __half* __restrict__ A, const __half* __restrict__ B,
           const float* __restrict__ aux, const __half* __restrict__ res, void* Cv,
           int ldA, int ldB, int ldC, int KITER,
           long long sA, long long sB, long long sC, long long sAux, long long sRes)
{
    extern __shared__ char smem[];
    const uint32_t sb0 = smem_u32(smem);
    const int tid = threadIdx.x;
    const int wid = tid >> 5, lane = tid & 31;
    const int r4 = lane >> 2, c4 = lane & 3;
    const int wm = wid >> 2, wn = wid & 3;
    const int m0w = wm * 64, n0w = wn * 32;

    const int bz = blockIdx.z;
    A += (size_t)bz * sA;
    B += (size_t)bz * sB;
    if (EPI == 1) aux += (size_t)bz * sAux;
    if (EPI == 2) res += (size_t)bz * sRes;

    const int row0 = blockIdx.y * 128;
    const int col0 = blockIdx.x * 128;

    const __half* Ab = A + (size_t)row0 * ldA;
    const __half* Bb = B + (size_t)col0 * ldB;

    // ldmatrix per-lane base addresses (row = lane&15, k-half-offset = (lane>>4)*8)
    const int lrow = lane & 15;
    const int lkh  = (lane >> 4) * 8;
    uint32_t aAddr[4], bAddr[2];
    #pragma unroll
    for (int mt = 0; mt < 4; mt++)
        aAddr[mt] = sb0 + (uint32_t)((m0w + mt * 16 + lrow) * TS_H + lkh) * 2;
    #pragma unroll
    for (int p = 0; p < 2; p++)
        bAddr[p] = sb0 + T_BYTES + (uint32_t)((n0w + p * 16 + lrow) * TS_H + lkh) * 2;

    float acc[4][4][4];
    #pragma unroll
    for (int i = 0; i < 4; i++)
        #pragma unroll
        for (int j = 0; j < 4; j++)
            #pragma unroll
            for (int t = 0; t < 4; t++) acc[i][j][t] = 0.0f;

    load_h(sb0, Ab, ldA, tid);
    load_h(sb0 + T_BYTES, Bb, ldB, tid);
    CPA_COMMIT();

    for (int it = 0; it < KITER; it++) {
        if (it + 1 < KITER) {
            uint32_t sn = sb0 + ((it + 1) & 1) * STAGE_BYTES;
            load_h(sn, Ab + (it + 1) * 64, ldA, tid);
            load_h(sn + T_BYTES, Bb + (size_t)(it + 1) * 64, ldB, tid);
            CPA_COMMIT();
            cpa_wait<1>();
        } else {
            cpa_wait<0>();
        }
        __syncthreads();

        const uint32_t so = (uint32_t)(it & 1) * STAGE_BYTES;

        #pragma unroll
        for (int kk = 0; kk < 4; kk++) {          // 4 x k16 steps; +16 halves each
            const uint32_t ko = so + kk * 32;      // 16 halves = 32 bytes
            uint32_t a[4][4], b[4][2];
            #pragma unroll
            for (int mt = 0; mt < 4; mt++)
                ldsm4(a[mt][0], a[mt][1], a[mt][2], a[mt][3], aAddr[mt] + ko);
            #pragma unroll
            for (int p = 0; p < 2; p++)
                ldsm4(b[2 * p][0], b[2 * p + 1][0], b[2 * p][1], b[2 * p + 1][1],
                      bAddr[p] + ko);
            #pragma unroll
            for (int mt = 0; mt < 4; mt++)
                #pragma unroll
                for (int nt = 0; nt < 4; nt++)
                    mma_f16(acc[mt][nt], a[mt], b[nt]);
        }
        __syncthreads();
    }

    // ---- epilogue ----
    #pragma unroll
    for (int mt = 0; mt < 4; mt++) {
        const int r0 = row0 + m0w + mt * 16 + r4;
        #pragma unroll
        for (int nt = 0; nt < 4; nt++) {
            const int col = col0 + n0w + nt * 8 + c4 * 2;
            float2 lo = make_float2(acc[mt][nt][0], acc[mt][nt][1]);   // row r0
            float2 hi = make_float2(acc[mt][nt][2], acc[mt][nt][3]);   // row r0+8
            if (EPI == 0) {
                __half* Ch = (__half*)Cv;
                float b0 = aux[col], b1 = aux[col + 1];
                __half2 ol = __floats2half2_rn(fmaxf(lo.x + b0, 0.0f), fmaxf(lo.y + b1, 0.0f));
                __half2 oh = __floats2half2_rn(fmaxf(hi.x + b0, 0.0f), fmaxf(hi.y + b1, 0.0f));
                *reinterpret_cast<__half2*>(&Ch[(size_t)r0 * ldC + col]) = ol;
                *reinterpret_cast<__half2*>(&Ch[(size_t)(r0 + 8) * ldC + col]) = oh;
            } else if (EPI == 1) {
                float* Cf = (float*)Cv + (size_t)bz * sC;
                float m0 = aux[col], m1 = aux[col + 1];
                lo.x = (m0 == 0.0f) ? NEGC : lo.x * 0.03125f;
                lo.y = (m1 == 0.0f) ? NEGC : lo.y * 0.03125f;
                hi.x = (m0 == 0.0f) ? NEGC : hi.x * 0.03125f;
                hi.y = (m1 == 0.0f) ? NEGC : hi.y * 0.03125f;
                *reinterpret_cast<float2*>(&Cf[(size_t)r0 * ldC + col]) = lo;
                *reinterpret_cast<float2*>(&Cf[(size_t)(r0 + 8) * ldC + col]) = hi;
            } else {
                float* Cf = (float*)Cv + (size_t)bz * sC;
                __half2 rl = *reinterpret_cast<const __half2*>(&res[(size_t)r0 * ldC + col]);
                __half2 rh = *reinterpret_cast<const __half2*>(&res[(size_t)(r0 + 8) * ldC + col]);
                lo.x += __low2float(rl);  lo.y += __high2float(rl);
                hi.x += __low2float(rh);  hi.y += __high2float(rh);
                *reinterpret_cast<float2*>(&Cf[(size_t)r0 * ldC + col]) = lo;
                *reinterpret_cast<float2*>(&Cf[(size_t)(r0 + 8) * ldC + col]) = hi;
            }
        }
    }
}

// ---------------------------------------------------------------------------
// softmax + query-mask; contiguous 8-element chunks per thread.
// ---------------------------------------------------------------------------
__global__ __launch_bounds__(256) void softmax_kernel() {
    const int r = blockIdx.x;
    const int b = r >> 11, qi = r & 2047;
    const float* srow = g_sc + (size_t)b * SS * SS + (size_t)qi * SS;
    __half* arow = g_at + (size_t)b * SS * SS + (size_t)qi * SS;
    const float mq = g_mask[r];
    const int t = threadIdx.x;

    float loc[8];
    float4 v0 = reinterpret_cast<const float4*>(srow)[t * 2];
    float4 v1 = reinterpret_cast<const float4*>(srow)[t * 2 + 1];
    loc[0] = v0.x; loc[1] = v0.y; loc[2] = v0.z; loc[3] = v0.w;
    loc[4] = v1.x; loc[5] = v1.y; loc[6] = v1.z; loc[7] = v1.w;

    float m = loc[0];
    #pragma unroll
    for (int i = 1; i < 8; i++) m = fmaxf(m, loc[i]);
    #pragma unroll
    for (int o = 16; o > 0; o >>= 1) m = fmaxf(m, __shfl_xor_sync(0xffffffffu, m, o));
    __shared__ float red[8];
    const int w = t >> 5, l = t & 31;
    if (l == 0) red[w] = m;
    __syncthreads();
    float bm = red[0];
    #pragma unroll
    for (int i = 1; i < 8; i++) bm = fmaxf(bm, red[i]);
    __syncthreads();
    float s = 0.0f;
    #pragma unroll
    for (int i = 0; i < 8; i++) { loc[i] = expf(loc[i] - bm); s += loc[i]; }
    #pragma unroll
    for (int o = 16; o > 0; o >>= 1) s += __shfl_xor_sync(0xffffffffu, s, o);
    if (l == 0) red[w] = s;
    __syncthreads();
    float bs = 0.0f;
    #pragma unroll
    for (int i = 0; i < 8; i++) bs += red[i];
    const float inv = mq / bs;

    __half2 h[4];
    #pragma unroll
    for (int i = 0; i < 4; i++)
        h[i] = __floats2half2_rn(loc[2 * i] * inv, loc[2 * i + 1] * inv);
    *reinterpret_cast<uint4*>(&arow[t * 8]) = *reinterpret_cast<uint4*>(h);
}

// ---------------------------------------------------------------------------
extern "C" void kernel_launch(void* const* d_in, const int* in_sizes, int n_in,
                              void* d_out, int out_size)
{
    const float* x  = (const float*)d_in[0];
    const float* Wq = (const float*)d_in[1];
    const float* bq = (const float*)d_in[2];
    const float* Wk = (const float*)d_in[3];
    const float* bk = (const float*)d_in[4];
    const float* Wv = (const float*)d_in[5];
    const float* bv = (const float*)d_in[6];
    float* out = (float*)d_out;

    __half *xh, *wh, *qh, *kh, *vh, *vth, *at;
    float *sc, *mask;
    cudaGetSymbolAddress((void**)&xh,   g_xh);
    cudaGetSymbolAddress((void**)&wh,   g_wh);
    cudaGetSymbolAddress((void**)&qh,   g_qh);
    cudaGetSymbolAddress((void**)&kh,   g_kh);
    cudaGetSymbolAddress((void**)&vh,   g_vh);
    cudaGetSymbolAddress((void**)&vth,  g_vth);
    cudaGetSymbolAddress((void**)&at,   g_at);
    cudaGetSymbolAddress((void**)&sc,   g_sc);
    cudaGetSymbolAddress((void**)&mask, g_mask);

    cudaFuncSetAttribute(hgemm<0>, cudaFuncAttributeMaxDynamicSharedMemorySize, SMEM_TOTAL);
    cudaFuncSetAttribute(hgemm<1>, cudaFuncAttributeMaxDynamicSharedMemorySize, SMEM_TOTAL);
    cudaFuncSetAttribute(hgemm<2>, cudaFuncAttributeMaxDynamicSharedMemorySize, SMEM_TOTAL);

    const int M = BB * SS;                    // 16384
    const long long SD  = (long long)SS * DD;
    const long long SS2 = (long long)SS * SS;

    // 0) input conversions
    cvt_f2h<<<592, 256>>>(x, xh, (int)((size_t)BB * SS * DD / 4));
    transpose_w_h<<<dim3(32, 32, 3), dim3(32, 8)>>>(Wq, Wk, Wv);

    // 1) masks (from original fp32 x)
    mask_kernel<<<M, 256>>>(x);

    // 2) QKV projections -> half
    {
        dim3 grd(DD / 128, M / 128, 1);
        hgemm<0><<<grd, 256, SMEM_TOTAL>>>(xh, wh + 0 * (size_t)DD * DD, bq, nullptr, qh,
                                           DD, DD, DD, DD / 64, 0, 0, 0, 0, 0);
        hgemm<0><<<grd, 256, SMEM_TOTAL>>>(xh, wh + 1 * (size_t)DD * DD, bk, nullptr, kh,
                                           DD, DD, DD, DD / 64, 0, 0, 0, 0, 0);
        hgemm<0><<<grd, 256, SMEM_TOTAL>>>(xh, wh + 2 * (size_t)DD * DD, bv, nullptr, vh,
                                           DD, DD, DD, DD / 64, 0, 0, 0, 0, 0);
    }

    // 3) v -> v^T per batch
    transpose_v_h<<<dim3(DD / 32, SS / 32, BB), dim3(32, 8)>>>();

    // 4) scores = q @ k^T / 32 + key mask -> fp32
    {
        dim3 grd(SS / 128, SS / 128, BB);
        hgemm<1><<<grd, 256, SMEM_TOTAL>>>(qh, kh, mask, nullptr, sc,
                                           DD, DD, SS, DD / 64,
                                           SD, SD, SS2, SS, 0);
    }

    // 5) softmax + query mask -> half attn
    softmax_kernel<<<M, 256>>>();

    // 6) out = attn @ v + q  (fp32 out)
    {
        dim3 grd(DD / 128, SS / 128, BB);
        hgemm<2><<<grd, 256, SMEM_TOTAL>>>(at, vth, nullptr, qh, out,
                                           SS, SS, DD, SS / 64,
                                           SS2, SD, SD, 0, SD);
    }
}